// round 7
// baseline (speedup 1.0000x reference)
#include <cuda_runtime.h>
#include <cstdint>

// CRPS loss, fused single kernel, packed f32x2, single-wave resident grid.
//   term1 = mean_i |s_i - y| ; term2 = sum_{i<j}|s_i - s_j| / 256
//   out   = mean_pixels (term1 - term2)
//
// samples: [16, 4, 1, 256, 256] f32 -> 16 planes of 262144 floats
// target:  [4, 1, 256, 256]     f32 -> 262144 floats
//
// 512 CTAs x 128 threads, each thread owns TWO float2 pixel-pairs (4 pixels),
// all 34 LDG.64 issued up front for max MLP; whole grid fits in one wave.

#define NS      16
#define NPIX    (4 * 1 * 256 * 256)     // 262144
#define THREADS 128
#define BLOCKS  512
#define NV2     (NPIX / 2)              // 131072 float2 groups
#define HALF    (BLOCKS * THREADS)      // 65536 = NV2/2

__device__ float        g_partial[BLOCKS];
__device__ unsigned int g_done = 0;

// ---- packed f32x2 helpers (sm_103a; ptxas never auto-emits these) ----
__device__ __forceinline__ uint64_t fadd2(uint64_t a, uint64_t b) {
    uint64_t r; asm("add.rn.f32x2 %0, %1, %2;" : "=l"(r) : "l"(a), "l"(b)); return r;
}
__device__ __forceinline__ uint64_t ffma2(uint64_t a, uint64_t b, uint64_t c) {
    uint64_t r; asm("fma.rn.f32x2 %0, %1, %2, %3;" : "=l"(r) : "l"(a), "l"(b), "l"(c)); return r;
}
__device__ __forceinline__ uint64_t fabs2(uint64_t a) {
    return a & 0x7FFFFFFF7FFFFFFFULL;        // sign-clear both lanes (alu pipe)
}
__device__ __forceinline__ uint64_t pack2(float2 v) {
    uint64_t r; asm("mov.b64 %0, {%1, %2};" : "=l"(r) : "f"(v.x), "f"(v.y)); return r;
}
__device__ __forceinline__ float2 unpack2(uint64_t v) {
    float lo, hi; asm("mov.b64 {%0, %1}, %2;" : "=f"(lo), "=f"(hi) : "l"(v));
    return make_float2(lo, hi);
}

#define NEG_ONE2 0xBF800000BF800000ULL       // {-1.0f, -1.0f}

__global__ __launch_bounds__(THREADS) void crps_fused_kernel(
    const float* __restrict__ samples,
    const float* __restrict__ target,
    float* __restrict__ out)
{
    const int tid = threadIdx.x;
    const int v0  = blockIdx.x * THREADS + tid;   // first float2 group
    const int v1  = v0 + HALF;                    // second float2 group

    // ---- all loads up front: 34 x LDG.64, coalesced, MLP=34 ----
    uint64_t sa[NS], sb[NS];
#pragma unroll
    for (int i = 0; i < NS; i++) {
        const float2* plane = reinterpret_cast<const float2*>(samples + (size_t)i * NPIX);
        sa[i] = pack2(plane[v0]);
        sb[i] = pack2(plane[v1]);
    }
    const uint64_t ya = pack2(reinterpret_cast<const float2*>(target)[v0]);
    const uint64_t yb = pack2(reinterpret_cast<const float2*>(target)[v1]);

    // ---- term1 for both groups, 2 packed accumulators each ----
    uint64_t t1a = 0, t1b = 0;
#pragma unroll
    for (int i = 0; i < NS; i += 2) {
        t1a = fadd2(t1a, fabs2(ffma2(ya, NEG_ONE2, sa[i])));
        t1b = fadd2(t1b, fabs2(ffma2(ya, NEG_ONE2, sa[i + 1])));
        t1a = fadd2(t1a, fabs2(ffma2(yb, NEG_ONE2, sb[i])));
        t1b = fadd2(t1b, fabs2(ffma2(yb, NEG_ONE2, sb[i + 1])));
    }

    // ---- term2: 120 pairs per group, interleaved, 4 packed accumulators ----
    uint64_t t2[4] = {0, 0, 0, 0};
    {
        int c = 0;
#pragma unroll
        for (int i = 0; i < NS; i++) {
#pragma unroll
            for (int j = i + 1; j < NS; j++) {
                t2[c & 3]       = fadd2(t2[c & 3],       fabs2(ffma2(sa[j], NEG_ONE2, sa[i])));
                t2[(c + 1) & 3] = fadd2(t2[(c + 1) & 3], fabs2(ffma2(sb[j], NEG_ONE2, sb[i])));
                c += 2;
            }
        }
    }

    const float2 p1 = unpack2(fadd2(t1a, t1b));
    const float2 p2 = unpack2(fadd2(fadd2(t2[0], t2[1]), fadd2(t2[2], t2[3])));
    float val = (p1.x + p1.y) * (1.0f / NS)
              - (p2.x + p2.y) * (1.0f / (NS * NS));

    // ---- block reduction (4 warps) ----
    __shared__ float warp_sum[THREADS / 32];
    float w = val;
#pragma unroll
    for (int off = 16; off > 0; off >>= 1)
        w += __shfl_down_sync(0xFFFFFFFFu, w, off);
    if ((tid & 31) == 0) warp_sum[tid >> 5] = w;
    __syncthreads();

    __shared__ bool is_last;
    if (tid == 0) {
        float b = (warp_sum[0] + warp_sum[1]) + (warp_sum[2] + warp_sum[3]);
        g_partial[blockIdx.x] = b;
        __threadfence();
        unsigned int ticket = atomicAdd(&g_done, 1u);
        is_last = (ticket == BLOCKS - 1);
    }
    __syncthreads();

    // ---- last block folds the 512 partials ----
    if (is_last) {
        float acc = 0.0f;
#pragma unroll
        for (int k = 0; k < BLOCKS / THREADS; k++)
            acc += g_partial[tid + k * THREADS];
#pragma unroll
        for (int off = 16; off > 0; off >>= 1)
            acc += __shfl_down_sync(0xFFFFFFFFu, acc, off);
        if ((tid & 31) == 0) warp_sum[tid >> 5] = acc;
        __syncthreads();
        if (tid == 0) {
            float total = (warp_sum[0] + warp_sum[1]) + (warp_sum[2] + warp_sum[3]);
            out[0] = total * (1.0f / NPIX);
            g_done = 0;                   // reset for next graph replay
        }
    }
}

extern "C" void kernel_launch(void* const* d_in, const int* in_sizes, int n_in,
                              void* d_out, int out_size)
{
    const float* samples = (const float*)d_in[0];
    const float* target  = (const float*)d_in[1];
    crps_fused_kernel<<<BLOCKS, THREADS>>>(samples, target, (float*)d_out);
}